// round 1
// baseline (speedup 1.0000x reference)
#include <cuda_runtime.h>
#include <cuda_bf16.h>
#include <cstdint>

// ---------------- problem constants ----------------
#define BATCH   64
#define FEAT    128
#define KDIM    2048
#define NDATA   100000
#define NSAMP   16385               // K+1
#define NPAIR   (BATCH * NSAMP)     // 1,048,640
#define NCE_T_INV (1.0f / 0.07f)
#define M_CONST (16384.0f / 100000.0f)
#define EPS_C   1e-7f

#define NSPLIT  64                  // k-split for embed GEMM (chunk = 32)
#define RTILE   64                  // rows of mem per logits block
#define NTILES  ((NDATA + RTILE - 1) / RTILE)   // 1563
#define SA      136                 // smem row stride in bf16 elems (272B: conflict-free ldmatrix)

// ---------------- device scratch (no allocations allowed) ----------------
__device__ float    g_partial[2][NSPLIT][BATCH * FEAT];  // 4.2 MB
__device__ uint32_t g_hb[2][BATCH * FEAT / 2];           // normalized v, bf16x2 packed
__device__ float    g_E[2][NDATA * BATCH];               // 51.2 MB exp(logit) matrix, [r][b]
__device__ float    g_G[2][NPAIR];                       // gathered sampled values
__device__ double   g_Z[2];                              // Z partial sums
__device__ double   g_L;                                 // loss sum

// ---------------- helpers ----------------
__device__ __forceinline__ void ldsm_x4(uint32_t* r, uint32_t addr) {
    asm volatile("ldmatrix.sync.aligned.m8n8.x4.shared.b16 {%0,%1,%2,%3}, [%4];"
                 : "=r"(r[0]), "=r"(r[1]), "=r"(r[2]), "=r"(r[3]) : "r"(addr));
}
__device__ __forceinline__ void mma_bf16(float* c, const uint32_t* a, uint32_t b0, uint32_t b1) {
    asm volatile("mma.sync.aligned.m16n8k16.row.col.f32.bf16.bf16.f32 "
                 "{%0,%1,%2,%3}, {%4,%5,%6,%7}, {%8,%9}, {%0,%1,%2,%3};"
                 : "+f"(c[0]), "+f"(c[1]), "+f"(c[2]), "+f"(c[3])
                 : "r"(a[0]), "r"(a[1]), "r"(a[2]), "r"(a[3]), "r"(b0), "r"(b1));
}

// ---------------- K0: zero accumulators ----------------
__global__ void k_zero() {
    g_Z[0] = 0.0; g_Z[1] = 0.0; g_L = 0.0;
}

// ---------------- K1: embed GEMM, split-K fp32 ----------------
// out[which][b][d] = sum_k feat[b][k] * w[d][k] over k-chunk of 32
__global__ void k_embed(const float* __restrict__ fs, const float* __restrict__ ft,
                        const float* __restrict__ ws, const float* __restrict__ wt) {
    const int which = blockIdx.x;
    const int split = blockIdx.y;
    const float* feat = which ? ft : fs;
    const float* w    = which ? wt : ws;
    const int k0 = split * 32;

    __shared__ float sf[BATCH * 33];
    __shared__ float sw[FEAT * 33];

    const int t = threadIdx.x;   // 256
    for (int i = t; i < BATCH * 32; i += 256) {
        int b = i >> 5, kk = i & 31;
        sf[b * 33 + kk] = feat[b * KDIM + k0 + kk];
    }
    for (int i = t; i < FEAT * 32; i += 256) {
        int d = i >> 5, kk = i & 31;
        sw[d * 33 + kk] = w[d * KDIM + k0 + kk];
    }
    __syncthreads();

    const int dg = t >> 4;         // 0..15 -> d0 = dg*8
    const int bg = t & 15;         // 0..15 -> b0 = bg*4
    const int d0 = dg * 8, b0 = bg * 4;

    float acc[4][8];
#pragma unroll
    for (int i = 0; i < 4; i++)
#pragma unroll
        for (int j = 0; j < 8; j++) acc[i][j] = 0.f;

#pragma unroll 4
    for (int kk = 0; kk < 32; kk++) {
        float fv[4], wv[8];
#pragma unroll
        for (int i = 0; i < 4; i++) fv[i] = sf[(b0 + i) * 33 + kk];
#pragma unroll
        for (int j = 0; j < 8; j++) wv[j] = sw[(d0 + j) * 33 + kk];
#pragma unroll
        for (int i = 0; i < 4; i++)
#pragma unroll
            for (int j = 0; j < 8; j++) acc[i][j] += fv[i] * wv[j];
    }

    float* outp = g_partial[which][split];
#pragma unroll
    for (int i = 0; i < 4; i++)
#pragma unroll
        for (int j = 0; j < 8; j++)
            outp[(b0 + i) * FEAT + d0 + j] = acc[i][j];
}

// ---------------- K2: reduce splits + bias + l2norm + pack bf16 ----------------
__global__ void k_norm(const float* __restrict__ bs, const float* __restrict__ bt) {
    const int which = blockIdx.x;
    const int b     = blockIdx.y;
    const int d     = threadIdx.x;  // 128
    const float* bias = which ? bt : bs;

    float s = 0.f;
#pragma unroll 8
    for (int sp = 0; sp < NSPLIT; sp++)
        s += g_partial[which][sp][b * FEAT + d];
    s += bias[d];

    float sq = s * s;
#pragma unroll
    for (int o = 16; o; o >>= 1) sq += __shfl_xor_sync(0xffffffffu, sq, o);
    __shared__ float wsum[4];
    if ((d & 31) == 0) wsum[d >> 5] = sq;
    __syncthreads();
    const float tot = wsum[0] + wsum[1] + wsum[2] + wsum[3];

    const float v = s * rsqrtf(tot);
    const float vn = __shfl_down_sync(0xffffffffu, v, 1);
    if ((d & 1) == 0) {
        __nv_bfloat162 h2 = __floats2bfloat162_rn(v, vn);
        g_hb[which][(b * FEAT + d) >> 1] = *reinterpret_cast<uint32_t*>(&h2);
    }
}

// ---------------- K3: dense logits GEMM (bf16 HMMA) + fused exp ----------------
// bank 0: v = hs vs mem_v2 ; bank 1: v = ht vs mem_v1
// E[bank][r][b] = exp(dot(mem[r], v[b]) / T)
__global__ __launch_bounds__(256) void k_logits(const float* __restrict__ mem_v1,
                                                const float* __restrict__ mem_v2) {
    const int bank = blockIdx.y;
    const float* mem = bank ? mem_v1 : mem_v2;
    const int r0 = blockIdx.x * RTILE;

    __shared__ __nv_bfloat16 As[RTILE * SA];   // mem tile,  64 x 128 bf16
    __shared__ __nv_bfloat16 Vs[BATCH * SA];   // v tile,    64 x 128 bf16

    const int t = threadIdx.x;

    // stage A (mem rows, fp32 -> bf16)
    for (int i = t; i < RTILE * 32; i += 256) {     // 32 float4 per row
        const int row = i >> 5, c4 = i & 31;
        const int gr = r0 + row;
        float4 f = make_float4(0.f, 0.f, 0.f, 0.f);
        if (gr < NDATA)
            f = *reinterpret_cast<const float4*>(&mem[(size_t)gr * FEAT + c4 * 4]);
        __nv_bfloat162 p0 = __floats2bfloat162_rn(f.x, f.y);
        __nv_bfloat162 p1 = __floats2bfloat162_rn(f.z, f.w);
        uint2 u;
        u.x = *reinterpret_cast<uint32_t*>(&p0);
        u.y = *reinterpret_cast<uint32_t*>(&p1);
        *reinterpret_cast<uint2*>(&As[row * SA + c4 * 4]) = u;
    }
    // stage V (already bf16-packed)
    for (int i = t; i < BATCH * 64; i += 256) {     // 64 u32 per row
        const int row = i >> 6, c2 = i & 63;
        *reinterpret_cast<uint32_t*>(&Vs[row * SA + c2 * 2]) = g_hb[bank][i];
    }
    __syncthreads();

    const uint32_t a_base = (uint32_t)__cvta_generic_to_shared(As);
    const uint32_t v_base = (uint32_t)__cvta_generic_to_shared(Vs);

    const int lane = t & 31, wid = t >> 5;
    const int wm = wid & 1;        // M half (rows wm*32..+31)
    const int wn = wid >> 1;       // b quarter (cols wn*16..+15)
    const int lr = lane & 7, q = lane >> 3;

    const int a_row = wm * 32 + lr + ((q & 1) << 3);
    const int a_kh  = (q >> 1) << 3;
    const int b_row = wn * 16 + lr + ((q >> 1) << 3);
    const int b_kh  = (q & 1) << 3;

    float acc[2][2][4];
#pragma unroll
    for (int i = 0; i < 2; i++)
#pragma unroll
        for (int j = 0; j < 2; j++)
#pragma unroll
            for (int e = 0; e < 4; e++) acc[i][j][e] = 0.f;

#pragma unroll
    for (int ks = 0; ks < 8; ks++) {
        const int k0 = ks * 16;
        uint32_t a0[4], a1[4], bb[4];
        ldsm_x4(a0, a_base + (uint32_t)((a_row) * SA + k0 + a_kh) * 2u);
        ldsm_x4(a1, a_base + (uint32_t)((a_row + 16) * SA + k0 + a_kh) * 2u);
        ldsm_x4(bb, v_base + (uint32_t)((b_row) * SA + k0 + b_kh) * 2u);
        mma_bf16(acc[0][0], a0, bb[0], bb[1]);
        mma_bf16(acc[0][1], a0, bb[2], bb[3]);
        mma_bf16(acc[1][0], a1, bb[0], bb[1]);
        mma_bf16(acc[1][1], a1, bb[2], bb[3]);
    }

    // epilogue: exp(logit/T) -> E[r][b]
    const int rrow = r0 + wm * 32 + (lane >> 2);
    const int col0 = wn * 16 + ((lane & 3) << 1);
    float* Eb = g_E[bank];
#pragma unroll
    for (int i = 0; i < 2; i++) {
#pragma unroll
        for (int j = 0; j < 2; j++) {
            const int c = col0 + j * 8;
            int r1 = rrow + i * 16;
            if (r1 < NDATA) {
                float2 o;
                o.x = __expf(acc[i][j][0] * NCE_T_INV);
                o.y = __expf(acc[i][j][1] * NCE_T_INV);
                *reinterpret_cast<float2*>(&Eb[(size_t)r1 * BATCH + c]) = o;
            }
            r1 += 8;
            if (r1 < NDATA) {
                float2 o;
                o.x = __expf(acc[i][j][2] * NCE_T_INV);
                o.y = __expf(acc[i][j][3] * NCE_T_INV);
                *reinterpret_cast<float2*>(&Eb[(size_t)r1 * BATCH + c]) = o;
            }
        }
    }
}

// ---------------- K4: gather sampled values + Z partial sums ----------------
__global__ void k_gather(const int* __restrict__ samp) {
    const int bank = blockIdx.y;
    const int p = blockIdx.x * 256 + threadIdx.x;
    float g = 0.f;
    if (p < NPAIR) {
        const int s = samp[p];
        const int b = p / NSAMP;
        g = g_E[bank][(size_t)s * BATCH + b];
        g_G[bank][p] = g;
    }
    float sum = g;
#pragma unroll
    for (int o = 16; o; o >>= 1) sum += __shfl_xor_sync(0xffffffffu, sum, o);
    __shared__ float ws[8];
    if ((threadIdx.x & 31) == 0) ws[threadIdx.x >> 5] = sum;
    __syncthreads();
    if (threadIdx.x == 0) {
        double tot = 0.0;
#pragma unroll
        for (int i = 0; i < 8; i++) tot += (double)ws[i];
        atomicAdd(&g_Z[bank], tot);
    }
}

// ---------------- K5: loss terms + reduce ----------------
__global__ void k_loss() {
    const int bank = blockIdx.y;
    const int p = blockIdx.x * 256 + threadIdx.x;
    const float z = (float)(g_Z[bank] * ((double)NDATA / (double)NPAIR));
    float term = 0.f;
    if (p < NPAIR) {
        const float x = g_G[bank][p] / z;
        const int b = p / NSAMP;
        const bool pos = (p - b * NSAMP) == 0;
        term = pos ? __logf(x / (x + M_CONST + EPS_C))
                   : __logf(M_CONST / (x + M_CONST + EPS_C));
    }
    float sum = term;
#pragma unroll
    for (int o = 16; o; o >>= 1) sum += __shfl_xor_sync(0xffffffffu, sum, o);
    __shared__ float ws[8];
    if ((threadIdx.x & 31) == 0) ws[threadIdx.x >> 5] = sum;
    __syncthreads();
    if (threadIdx.x == 0) {
        double tot = 0.0;
#pragma unroll
        for (int i = 0; i < 8; i++) tot += (double)ws[i];
        atomicAdd(&g_L, tot);
    }
}

// ---------------- K6: final scalar ----------------
__global__ void k_final(float* __restrict__ out) {
    out[0] = (float)(-g_L * (1.0 / (double)BATCH));
}

// ---------------- launcher ----------------
extern "C" void kernel_launch(void* const* d_in, const int* in_sizes, int n_in,
                              void* d_out, int out_size) {
    const float* feat_s     = (const float*)d_in[0];
    const float* feat_t     = (const float*)d_in[1];
    // d_in[2] = idx (unused; positives already in sample_idx[:,0])
    const int*   sample_idx = (const int*)d_in[3];
    const float* w_s        = (const float*)d_in[4];
    const float* b_s        = (const float*)d_in[5];
    const float* w_t        = (const float*)d_in[6];
    const float* b_t        = (const float*)d_in[7];
    const float* mem_v1     = (const float*)d_in[8];
    const float* mem_v2     = (const float*)d_in[9];
    float* out = (float*)d_out;

    k_zero<<<1, 1>>>();
    k_embed<<<dim3(2, NSPLIT), 256>>>(feat_s, feat_t, w_s, w_t);
    k_norm<<<dim3(2, BATCH), 128>>>(b_s, b_t);
    k_logits<<<dim3(NTILES, 2), 256>>>(mem_v1, mem_v2);
    const int gblocks = (NPAIR + 255) / 256;
    k_gather<<<dim3(gblocks, 2), 256>>>(sample_idx);
    k_loss<<<dim3(gblocks, 2), 256>>>();
    k_final<<<1, 1>>>(out);
}

// round 2
// speedup vs baseline: 1.2158x; 1.2158x over previous
#include <cuda_runtime.h>
#include <cuda_bf16.h>
#include <cstdint>

// ---------------- problem constants ----------------
#define BATCH   64
#define FEAT    128
#define KDIM    2048
#define NDATA   100000
#define NSAMP   16385               // K+1
#define NPAIR   (BATCH * NSAMP)     // 1,048,640
#define NCE_T_INV (1.0f / 0.07f)
#define M_CONST (16384.0f / 100000.0f)
#define EPS_C   1e-7f

#define NSPLIT  64                  // k-split for embed GEMM (chunk = 32)
#define RBLK    128                 // rows of mem per logits block (8 warps x m16)
#define NBLK    ((NDATA + RBLK - 1) / RBLK)     // 782
#define SA      136                 // smem row stride in bf16 elems (conflict-free ldmatrix)

#define GATHER_BLOCKS 1024

// ---------------- device scratch (no allocations allowed) ----------------
__device__ float          g_partial[2][NSPLIT][BATCH * FEAT];  // 4.2 MB
__device__ uint32_t       g_hb[2][BATCH * FEAT / 2];           // normalized v, bf16x2 packed
__device__ __nv_bfloat16  g_E[2][(size_t)NDATA * BATCH];       // 25.6 MB exp(logit), [r][b]
__device__ float          g_G[2][NPAIR];                       // gathered sampled values
__device__ double         g_Z[2];                              // Z partial sums
__device__ double         g_L;                                 // loss sum

// ---------------- helpers ----------------
__device__ __forceinline__ void ldsm_x4(uint32_t* r, uint32_t addr) {
    asm volatile("ldmatrix.sync.aligned.m8n8.x4.shared.b16 {%0,%1,%2,%3}, [%4];"
                 : "=r"(r[0]), "=r"(r[1]), "=r"(r[2]), "=r"(r[3]) : "r"(addr));
}
__device__ __forceinline__ void mma_bf16(float* c, const uint32_t* a, uint32_t b0, uint32_t b1) {
    asm volatile("mma.sync.aligned.m16n8k16.row.col.f32.bf16.bf16.f32 "
                 "{%0,%1,%2,%3}, {%4,%5,%6,%7}, {%8,%9}, {%0,%1,%2,%3};"
                 : "+f"(c[0]), "+f"(c[1]), "+f"(c[2]), "+f"(c[3])
                 : "r"(a[0]), "r"(a[1]), "r"(a[2]), "r"(a[3]), "r"(b0), "r"(b1));
}
__device__ __forceinline__ uint32_t pack_bf2(float x, float y) {
    __nv_bfloat162 h2 = __floats2bfloat162_rn(x, y);
    return *reinterpret_cast<uint32_t*>(&h2);
}

// ---------------- K1: embed GEMM, split-K fp32 (+ zero init) ----------------
__global__ void k_embed(const float* __restrict__ fs, const float* __restrict__ ft,
                        const float* __restrict__ ws, const float* __restrict__ wt) {
    if (blockIdx.x == 0 && blockIdx.y == 0 && threadIdx.x == 0) {
        g_Z[0] = 0.0; g_Z[1] = 0.0; g_L = 0.0;
    }
    const int which = blockIdx.x;
    const int split = blockIdx.y;
    const float* feat = which ? ft : fs;
    const float* w    = which ? wt : ws;
    const int k0 = split * 32;

    __shared__ float sf[BATCH * 33];
    __shared__ float sw[FEAT * 33];

    const int t = threadIdx.x;   // 256
    for (int i = t; i < BATCH * 32; i += 256) {
        int b = i >> 5, kk = i & 31;
        sf[b * 33 + kk] = feat[b * KDIM + k0 + kk];
    }
    for (int i = t; i < FEAT * 32; i += 256) {
        int d = i >> 5, kk = i & 31;
        sw[d * 33 + kk] = w[d * KDIM + k0 + kk];
    }
    __syncthreads();

    const int dg = t >> 4, bg = t & 15;
    const int d0 = dg * 8, b0 = bg * 4;

    float acc[4][8];
#pragma unroll
    for (int i = 0; i < 4; i++)
#pragma unroll
        for (int j = 0; j < 8; j++) acc[i][j] = 0.f;

#pragma unroll 4
    for (int kk = 0; kk < 32; kk++) {
        float fv[4], wv[8];
#pragma unroll
        for (int i = 0; i < 4; i++) fv[i] = sf[(b0 + i) * 33 + kk];
#pragma unroll
        for (int j = 0; j < 8; j++) wv[j] = sw[(d0 + j) * 33 + kk];
#pragma unroll
        for (int i = 0; i < 4; i++)
#pragma unroll
            for (int j = 0; j < 8; j++) acc[i][j] += fv[i] * wv[j];
    }

    float* outp = g_partial[which][split];
#pragma unroll
    for (int i = 0; i < 4; i++)
#pragma unroll
        for (int j = 0; j < 8; j++)
            outp[(b0 + i) * FEAT + d0 + j] = acc[i][j];
}

// ---------------- K2: reduce splits + bias + l2norm + pack bf16 ----------------
__global__ void k_norm(const float* __restrict__ bs, const float* __restrict__ bt) {
    const int which = blockIdx.x;
    const int b     = blockIdx.y;
    const int d     = threadIdx.x;  // 128
    const float* bias = which ? bt : bs;

    float s = 0.f;
#pragma unroll 8
    for (int sp = 0; sp < NSPLIT; sp++)
        s += g_partial[which][sp][b * FEAT + d];
    s += bias[d];

    float sq = s * s;
#pragma unroll
    for (int o = 16; o; o >>= 1) sq += __shfl_xor_sync(0xffffffffu, sq, o);
    __shared__ float wsum[4];
    if ((d & 31) == 0) wsum[d >> 5] = sq;
    __syncthreads();
    const float tot = wsum[0] + wsum[1] + wsum[2] + wsum[3];

    const float v = s * rsqrtf(tot);
    const float vn = __shfl_down_sync(0xffffffffu, v, 1);
    if ((d & 1) == 0)
        g_hb[which][(b * FEAT + d) >> 1] = pack_bf2(v, vn);
}

// ---------------- K3: dense logits GEMM, A direct-to-register, pipelined ----------------
// bank 0: v = hs vs mem_v2 ; bank 1: v = ht vs mem_v1
// E[bank][r][b] = bf16( exp(dot(mem[r], v[b]) / T) )
__global__ __launch_bounds__(256, 2) void k_logits(const float* __restrict__ mem_v1,
                                                   const float* __restrict__ mem_v2) {
    const int bank = blockIdx.y;
    const float* __restrict__ mem = bank ? mem_v1 : mem_v2;
    const int r_base = blockIdx.x * RBLK;

    __shared__ __nv_bfloat16 Vs[BATCH * SA];   // v tile, 64 x 128 bf16

    const int t = threadIdx.x;
    // stage V (already bf16-packed): 64 rows x 64 u32
    for (int i = t; i < BATCH * 64; i += 256) {
        const int row = i >> 6, c2 = i & 63;
        *reinterpret_cast<uint32_t*>(&Vs[row * SA + c2 * 2]) = g_hb[bank][i];
    }
    __syncthreads();

    const uint32_t v_base = (uint32_t)__cvta_generic_to_shared(Vs);
    const int lane = t & 31, warp = t >> 5;
    const int lr = lane & 7, q = lane >> 3;

    // A rows for this lane's fragments
    const int row0 = r_base + warp * 16 + (lane >> 2);
    const int row1 = row0 + 8;
    const int rc0 = row0 < NDATA ? row0 : NDATA - 1;   // clamp for safe loads
    const int rc1 = row1 < NDATA ? row1 : NDATA - 1;
    const float* p0 = mem + (size_t)rc0 * FEAT + (lane & 3) * 2;
    const float* p1 = mem + (size_t)rc1 * FEAT + (lane & 3) * 2;

    // B ldmatrix addressing
    const int b_row = lr + ((q >> 1) << 3);
    const int b_kh  = (q & 1) << 3;

    float acc[8][4];
#pragma unroll
    for (int f = 0; f < 8; f++)
#pragma unroll
        for (int e = 0; e < 4; e++) acc[f][e] = 0.f;

    float2 buf[2][4];
#define LOADK(s, ks) {                                              \
        buf[s][0] = *reinterpret_cast<const float2*>(p0 + (ks) * 16);     \
        buf[s][1] = *reinterpret_cast<const float2*>(p1 + (ks) * 16);     \
        buf[s][2] = *reinterpret_cast<const float2*>(p0 + (ks) * 16 + 8); \
        buf[s][3] = *reinterpret_cast<const float2*>(p1 + (ks) * 16 + 8); }

    LOADK(0, 0);
    LOADK(1, 1);

#pragma unroll
    for (int ks = 0; ks < 8; ks++) {
        const int s = ks & 1;
        uint32_t a[4];
#pragma unroll
        for (int e = 0; e < 4; e++) a[e] = pack_bf2(buf[s][e].x, buf[s][e].y);
        if (ks < 6) LOADK(s, ks + 2);

        const int k0 = ks * 16;
#pragma unroll
        for (int nt = 0; nt < 4; nt++) {
            uint32_t bb[4];
            ldsm_x4(bb, v_base + (uint32_t)((nt * 16 + b_row) * SA + k0 + b_kh) * 2u);
            mma_bf16(acc[nt * 2 + 0], a, bb[0], bb[1]);
            mma_bf16(acc[nt * 2 + 1], a, bb[2], bb[3]);
        }
    }
#undef LOADK

    // epilogue: exp(logit/T) -> bf16 E[r][b]
    uint32_t* Eb = reinterpret_cast<uint32_t*>(g_E[bank]);
    const int cbase = (lane & 3) * 2;
#pragma unroll
    for (int f = 0; f < 8; f++) {
        const int c = (f >> 1) * 16 + (f & 1) * 8 + cbase;
        if (row0 < NDATA)
            Eb[(size_t)row0 * (BATCH / 2) + (c >> 1)] =
                pack_bf2(__expf(acc[f][0] * NCE_T_INV), __expf(acc[f][1] * NCE_T_INV));
        if (row1 < NDATA)
            Eb[(size_t)row1 * (BATCH / 2) + (c >> 1)] =
                pack_bf2(__expf(acc[f][2] * NCE_T_INV), __expf(acc[f][3] * NCE_T_INV));
    }
}

// ---------------- K4: gather sampled values + Z partial sums ----------------
__global__ void k_gather(const int* __restrict__ samp) {
    const int bank = blockIdx.y;
    float lsum = 0.f;
    for (int p = blockIdx.x * 256 + threadIdx.x; p < NPAIR; p += 256 * GATHER_BLOCKS) {
        const int s = samp[p];
        const int b = p / NSAMP;
        const float g = __bfloat162float(g_E[bank][(size_t)s * BATCH + b]);
        g_G[bank][p] = g;
        lsum += g;
    }
#pragma unroll
    for (int o = 16; o; o >>= 1) lsum += __shfl_xor_sync(0xffffffffu, lsum, o);
    __shared__ float ws[8];
    if ((threadIdx.x & 31) == 0) ws[threadIdx.x >> 5] = lsum;
    __syncthreads();
    if (threadIdx.x == 0) {
        double tot = 0.0;
#pragma unroll
        for (int i = 0; i < 8; i++) tot += (double)ws[i];
        atomicAdd(&g_Z[bank], tot);
    }
}

// ---------------- K5: loss terms + reduce ----------------
__global__ void k_loss() {
    const int bank = blockIdx.y;
    const float z = (float)(g_Z[bank] * ((double)NDATA / (double)NPAIR));
    const float zinv = 1.0f / z;
    float lsum = 0.f;
    for (int p = blockIdx.x * 256 + threadIdx.x; p < NPAIR; p += 256 * GATHER_BLOCKS) {
        const float x = g_G[bank][p] * zinv;
        const int b = p / NSAMP;
        const bool pos = (p - b * NSAMP) == 0;
        lsum += pos ? __logf(x / (x + M_CONST + EPS_C))
                    : __logf(M_CONST / (x + M_CONST + EPS_C));
    }
#pragma unroll
    for (int o = 16; o; o >>= 1) lsum += __shfl_xor_sync(0xffffffffu, lsum, o);
    __shared__ float ws[8];
    if ((threadIdx.x & 31) == 0) ws[threadIdx.x >> 5] = lsum;
    __syncthreads();
    if (threadIdx.x == 0) {
        double tot = 0.0;
#pragma unroll
        for (int i = 0; i < 8; i++) tot += (double)ws[i];
        atomicAdd(&g_L, tot);
    }
}

// ---------------- K6: final scalar ----------------
__global__ void k_final(float* __restrict__ out) {
    out[0] = (float)(-g_L * (1.0 / (double)BATCH));
}

// ---------------- launcher ----------------
extern "C" void kernel_launch(void* const* d_in, const int* in_sizes, int n_in,
                              void* d_out, int out_size) {
    const float* feat_s     = (const float*)d_in[0];
    const float* feat_t     = (const float*)d_in[1];
    // d_in[2] = idx (unused; positives already in sample_idx[:,0])
    const int*   sample_idx = (const int*)d_in[3];
    const float* w_s        = (const float*)d_in[4];
    const float* b_s        = (const float*)d_in[5];
    const float* w_t        = (const float*)d_in[6];
    const float* b_t        = (const float*)d_in[7];
    const float* mem_v1     = (const float*)d_in[8];
    const float* mem_v2     = (const float*)d_in[9];
    float* out = (float*)d_out;

    k_embed<<<dim3(2, NSPLIT), 256>>>(feat_s, feat_t, w_s, w_t);
    k_norm<<<dim3(2, BATCH), 128>>>(b_s, b_t);
    k_logits<<<dim3(NBLK, 2), 256>>>(mem_v1, mem_v2);
    k_gather<<<dim3(GATHER_BLOCKS, 2), 256>>>(sample_idx);
    k_loss<<<dim3(GATHER_BLOCKS, 2), 256>>>();
    k_final<<<1, 1>>>(out);
}

// round 3
// speedup vs baseline: 1.4063x; 1.1567x over previous
#include <cuda_runtime.h>
#include <cuda_bf16.h>
#include <cstdint>

// ---------------- problem constants ----------------
#define BATCH   64
#define FEAT    128
#define KDIM    2048
#define NDATA   100000
#define NSAMP   16385               // K+1
#define NPAIR   (BATCH * NSAMP)     // 1,048,640
#define NCE_T_INV (1.0f / 0.07f)
#define M_CONST (16384.0f / 100000.0f)
#define EPS_C   1e-7f

#define NSPLIT  64                  // embed split-K (chunk 32)
#define RBLK    128                 // rows per logits tile
#define NTILE   ((NDATA + RBLK - 1) / RBLK)   // 782
#define SA      136                 // smem row stride (bf16 elems)

#define NBB     148                 // blocks per bank
#define NB      (2 * NBB)           // 296 total blocks = 148 SMs x occ 2
#define GSTRIDE (NBB * 256)         // 37888 pairs/step per bank
#define GITER   28                  // ceil(NPAIR / GSTRIDE)

// ---------------- device scratch (all zero-init; reset at end of each call) ----------------
__device__ float          g_partial[2][NSPLIT][BATCH * FEAT];
__device__ uint32_t       g_hb[2][BATCH * FEAT / 2];
__device__ __nv_bfloat16  g_E[2][(size_t)NDATA * BATCH];
__device__ double         g_Z[2];
__device__ double         g_L;
__device__ int            g_bars[4];
__device__ int            g_tick[2];
__device__ int            g_done;

// ---------------- helpers ----------------
__device__ __forceinline__ void ldsm_x4(uint32_t* r, uint32_t addr) {
    asm volatile("ldmatrix.sync.aligned.m8n8.x4.shared.b16 {%0,%1,%2,%3}, [%4];"
                 : "=r"(r[0]), "=r"(r[1]), "=r"(r[2]), "=r"(r[3]) : "r"(addr));
}
__device__ __forceinline__ void mma_bf16(float* c, const uint32_t* a, uint32_t b0, uint32_t b1) {
    asm volatile("mma.sync.aligned.m16n8k16.row.col.f32.bf16.bf16.f32 "
                 "{%0,%1,%2,%3}, {%4,%5,%6,%7}, {%8,%9}, {%0,%1,%2,%3};"
                 : "+f"(c[0]), "+f"(c[1]), "+f"(c[2]), "+f"(c[3])
                 : "r"(a[0]), "r"(a[1]), "r"(a[2]), "r"(a[3]), "r"(b0), "r"(b1));
}
__device__ __forceinline__ uint32_t pack_bf2(float x, float y) {
    __nv_bfloat162 h2 = __floats2bfloat162_rn(x, y);
    return *reinterpret_cast<uint32_t*>(&h2);
}
__device__ __forceinline__ float ld_e_cg(const __nv_bfloat16* p) {
    unsigned short v;
    asm volatile("ld.global.cg.u16 %0, [%1];" : "=h"(v) : "l"(p));
    __nv_bfloat16 b;
    *reinterpret_cast<unsigned short*>(&b) = v;
    return __bfloat162float(b);
}
// grid-wide spin barrier (all NB blocks co-resident by construction)
__device__ __forceinline__ void gbar(int idx) {
    __syncthreads();
    if (threadIdx.x == 0) {
        __threadfence();
        atomicAdd(&g_bars[idx], 1);
        while (*(volatile int*)&g_bars[idx] < NB) __nanosleep(100);
    }
    __syncthreads();
}

// ================= the one kernel =================
__global__ __launch_bounds__(256, 2) void k_fused(
    const float* __restrict__ fs, const float* __restrict__ ft,
    const int*   __restrict__ samp,
    const float* __restrict__ ws, const float* __restrict__ bsv,
    const float* __restrict__ wt, const float* __restrict__ btv,
    const float* __restrict__ mem_v1, const float* __restrict__ mem_v2,
    float* __restrict__ out)
{
    __shared__ __align__(16) char s_raw[25600];
    __shared__ float s_red[8];
    __shared__ int   s_tile;
    __shared__ float s_z;

    const int u   = blockIdx.x;
    const int tid = threadIdx.x;

    // ---------------- P0: embed GEMM, split-K fp32 (blocks 0..127) ----------------
    if (u < 2 * NSPLIT) {
        const int which = u >> 6;
        const int split = u & 63;
        const float* feat = which ? ft : fs;
        const float* w    = which ? wt : ws;
        const int k0 = split * 32;

        float* sf = reinterpret_cast<float*>(s_raw);            // 64 x 33
        float* sw = sf + BATCH * 33;                            // 128 x 33

        for (int i = tid; i < BATCH * 32; i += 256) {
            int b = i >> 5, kk = i & 31;
            sf[b * 33 + kk] = feat[b * KDIM + k0 + kk];
        }
        for (int i = tid; i < FEAT * 32; i += 256) {
            int d = i >> 5, kk = i & 31;
            sw[d * 33 + kk] = w[d * KDIM + k0 + kk];
        }
        __syncthreads();

        const int d0 = (tid >> 4) * 8, b0 = (tid & 15) * 4;
        float acc[4][8];
#pragma unroll
        for (int i = 0; i < 4; i++)
#pragma unroll
            for (int j = 0; j < 8; j++) acc[i][j] = 0.f;

#pragma unroll 4
        for (int kk = 0; kk < 32; kk++) {
            float fv[4], wv[8];
#pragma unroll
            for (int i = 0; i < 4; i++) fv[i] = sf[(b0 + i) * 33 + kk];
#pragma unroll
            for (int j = 0; j < 8; j++) wv[j] = sw[(d0 + j) * 33 + kk];
#pragma unroll
            for (int i = 0; i < 4; i++)
#pragma unroll
                for (int j = 0; j < 8; j++) acc[i][j] += fv[i] * wv[j];
        }
        float* outp = g_partial[which][split];
#pragma unroll
        for (int i = 0; i < 4; i++)
#pragma unroll
            for (int j = 0; j < 8; j++)
                outp[(b0 + i) * FEAT + d0 + j] = acc[i][j];
    }
    gbar(0);

    // ---------------- P1: reduce splits + bias + l2norm + pack bf16 (blocks 0..127) ----------------
    if (u < 128) {
        const int which = u >> 6;
        const int b     = u & 63;
        const float* bias = which ? btv : bsv;
        float s = 0.f, v = 0.f;
        if (tid < 128) {
            const int d = tid;
#pragma unroll 8
            for (int sp = 0; sp < NSPLIT; sp++)
                s += __ldcg(&g_partial[which][sp][b * FEAT + d]);
            s += bias[d];
            float sq = s * s;
#pragma unroll
            for (int o = 16; o; o >>= 1) sq += __shfl_xor_sync(0xffffffffu, sq, o);
            if ((d & 31) == 0) s_red[d >> 5] = sq;
        }
        __syncthreads();
        if (tid < 128) {
            const float tot = s_red[0] + s_red[1] + s_red[2] + s_red[3];
            v = s * rsqrtf(tot);
            const float vn = __shfl_down_sync(0xffffffffu, v, 1);
            if ((tid & 1) == 0)
                g_hb[which][(b * FEAT + tid) >> 1] = pack_bf2(v, vn);
        }
    }
    gbar(1);

    // ---------------- P2: dense logits GEMM + fused exp, ticket-scheduled ----------------
    const int bank = (u >= NBB) ? 1 : 0;
    {
        const float* __restrict__ mem = bank ? mem_v1 : mem_v2;
        uint16_t* Vs = reinterpret_cast<uint16_t*>(s_raw);       // 64 x SA bf16

        for (int i = tid; i < BATCH * 64; i += 256) {
            const int row = i >> 6, c2 = i & 63;
            *reinterpret_cast<uint32_t*>(&Vs[row * SA + c2 * 2]) =
                __ldcg(&g_hb[bank][i]);
        }
        __syncthreads();

        const uint32_t v_base = (uint32_t)__cvta_generic_to_shared(Vs);
        const int lane = tid & 31, warp = tid >> 5;
        const int lr = lane & 7, q = lane >> 3;
        const int b_row = lr + ((q >> 1) << 3);
        const int b_kh  = (q & 1) << 3;
        uint32_t* Eb = reinterpret_cast<uint32_t*>(g_E[bank]);

        for (;;) {
            if (tid == 0) s_tile = atomicAdd(&g_tick[bank], 1);
            __syncthreads();
            const int tile = s_tile;
            if (tile >= NTILE) break;

            const int r_base = tile * RBLK;
            const int row0 = r_base + warp * 16 + (lane >> 2);
            const int row1 = row0 + 8;
            const int rc0 = row0 < NDATA ? row0 : NDATA - 1;
            const int rc1 = row1 < NDATA ? row1 : NDATA - 1;
            const float* p0 = mem + (size_t)rc0 * FEAT + (lane & 3) * 2;
            const float* p1 = mem + (size_t)rc1 * FEAT + (lane & 3) * 2;

            float acc[8][4];
#pragma unroll
            for (int f = 0; f < 8; f++)
#pragma unroll
                for (int e = 0; e < 4; e++) acc[f][e] = 0.f;

            float2 buf[2][4];
#define LOADK(s, ks) {                                                    \
            buf[s][0] = *reinterpret_cast<const float2*>(p0 + (ks) * 16);     \
            buf[s][1] = *reinterpret_cast<const float2*>(p1 + (ks) * 16);     \
            buf[s][2] = *reinterpret_cast<const float2*>(p0 + (ks) * 16 + 8); \
            buf[s][3] = *reinterpret_cast<const float2*>(p1 + (ks) * 16 + 8); }
            LOADK(0, 0);
            LOADK(1, 1);

#pragma unroll
            for (int ks = 0; ks < 8; ks++) {
                const int s = ks & 1;
                uint32_t a[4];
#pragma unroll
                for (int e = 0; e < 4; e++) a[e] = pack_bf2(buf[s][e].x, buf[s][e].y);
                if (ks < 6) LOADK(s, ks + 2);
                const int k0 = ks * 16;
#pragma unroll
                for (int nt = 0; nt < 4; nt++) {
                    uint32_t bb[4];
                    ldsm_x4(bb, v_base + (uint32_t)((nt * 16 + b_row) * SA + k0 + b_kh) * 2u);
                    mma_bf16(acc[nt * 2 + 0], a, bb[0], bb[1]);
                    mma_bf16(acc[nt * 2 + 1], a, bb[2], bb[3]);
                }
            }
#undef LOADK
            const int cbase = (lane & 3) * 2;
#pragma unroll
            for (int f = 0; f < 8; f++) {
                const int c = (f >> 1) * 16 + (f & 1) * 8 + cbase;
                if (row0 < NDATA)
                    Eb[(size_t)row0 * (BATCH / 2) + (c >> 1)] =
                        pack_bf2(__expf(acc[f][0] * NCE_T_INV), __expf(acc[f][1] * NCE_T_INV));
                if (row1 < NDATA)
                    Eb[(size_t)row1 * (BATCH / 2) + (c >> 1)] =
                        pack_bf2(__expf(acc[f][2] * NCE_T_INV), __expf(acc[f][3] * NCE_T_INV));
            }
            __syncthreads();
        }
    }
    gbar(2);

    // ---------------- P3: gather into registers + Z ----------------
    const int bx = u - bank * NBB;
    const int pbase = bx * 256 + tid;
    float gv[GITER];
    {
#pragma unroll
        for (int i = 0; i < GITER; i++) {
            const int p = pbase + i * GSTRIDE;
            gv[i] = 0.f;
            if (p < NPAIR) {
                const int s = __ldg(&samp[p]);
                const int b = p / NSAMP;
                gv[i] = ld_e_cg(&g_E[bank][(size_t)s * BATCH + b]);
            }
        }
        float lsum = 0.f;
#pragma unroll
        for (int i = 0; i < GITER; i++) lsum += gv[i];
#pragma unroll
        for (int o = 16; o; o >>= 1) lsum += __shfl_xor_sync(0xffffffffu, lsum, o);
        if ((tid & 31) == 0) s_red[tid >> 5] = lsum;
        __syncthreads();
        if (tid == 0) {
            double tot = 0.0;
#pragma unroll
            for (int i = 0; i < 8; i++) tot += (double)s_red[i];
            atomicAdd(&g_Z[bank], tot);
        }
    }
    gbar(3);

    // ---------------- P4: loss from registers (batched logs) ----------------
    {
        if (tid == 0) {
            const double Zv = *(volatile double*)&g_Z[bank];
            s_z = (float)(Zv * ((double)NDATA / (double)NPAIR));
        }
        __syncthreads();
        const float zinv = 1.0f / s_z;

        float lsum = 0.f;
        float pn = 1.f, pd = 1.f;
#pragma unroll
        for (int i = 0; i < GITER; i++) {
            const int p = pbase + i * GSTRIDE;
            if (p < NPAIR) {
                const float x = gv[i] * zinv;
                const int b = p / NSAMP;
                const bool pos = (p - b * NSAMP) == 0;
                pn *= pos ? x : M_CONST;
                pd *= x + M_CONST + EPS_C;
            }
            if (i == 13 || i == GITER - 1) {      // two batches of 14
                lsum += __logf(pn / pd);
                pn = 1.f; pd = 1.f;
            }
        }
#pragma unroll
        for (int o = 16; o; o >>= 1) lsum += __shfl_xor_sync(0xffffffffu, lsum, o);
        __syncthreads();
        if ((tid & 31) == 0) s_red[tid >> 5] = lsum;
        __syncthreads();
        if (tid == 0) {
            double tot = 0.0;
#pragma unroll
            for (int i = 0; i < 8; i++) tot += (double)s_red[i];
            atomicAdd(&g_L, tot);
            __threadfence();
            const int v = atomicAdd(&g_done, 1);
            if (v == NB - 1) {
                const double L = *(volatile double*)&g_L;
                out[0] = (float)(-L / (double)BATCH);
                // reset all state for the next graph replay
                g_Z[0] = 0.0; g_Z[1] = 0.0; g_L = 0.0;
                g_bars[0] = g_bars[1] = g_bars[2] = g_bars[3] = 0;
                g_tick[0] = g_tick[1] = 0;
                g_done = 0;
                __threadfence();
            }
        }
    }
}

// ---------------- launcher: ONE kernel ----------------
extern "C" void kernel_launch(void* const* d_in, const int* in_sizes, int n_in,
                              void* d_out, int out_size) {
    const float* feat_s     = (const float*)d_in[0];
    const float* feat_t     = (const float*)d_in[1];
    // d_in[2] = idx (unused; positives already in sample_idx[:,0])
    const int*   sample_idx = (const int*)d_in[3];
    const float* w_s        = (const float*)d_in[4];
    const float* b_s        = (const float*)d_in[5];
    const float* w_t        = (const float*)d_in[6];
    const float* b_t        = (const float*)d_in[7];
    const float* mem_v1     = (const float*)d_in[8];
    const float* mem_v2     = (const float*)d_in[9];
    float* out = (float*)d_out;

    k_fused<<<NB, 256>>>(feat_s, feat_t, sample_idx,
                         w_s, b_s, w_t, b_t, mem_v1, mem_v2, out);
}

// round 4
// speedup vs baseline: 1.6175x; 1.1502x over previous
#include <cuda_runtime.h>
#include <cuda_bf16.h>
#include <cstdint>

// ---------------- problem constants ----------------
#define BATCH   64
#define FEAT    128
#define KDIM    2048
#define NDATA   100000
#define NSAMP   16385               // K+1
#define NPAIR   (BATCH * NSAMP)     // 1,048,640
#define NCE_T_INV (1.0f / 0.07f)
#define M_CONST (16384.0f / 100000.0f)
#define EPS_C   1e-7f

#define NSPLIT  64                  // embed split-K (chunk 32)
#define RBLK    128                 // rows per logits tile
#define NTILE   ((NDATA + RBLK - 1) / RBLK)   // 782
#define SA      136                 // smem row stride (bf16 elems)

#define NBB     148                 // blocks per bank
#define NB      (2 * NBB)           // 296 total blocks = 148 SMs x occ 2
#define GSTRIDE (NBB * 256)         // 37888 pairs/step per bank
#define GITER   28                  // ceil(NPAIR / GSTRIDE)

// ---------------- device scratch (zero-init; reset at end of each call) ----------------
__device__ float          g_partial[2][NSPLIT][BATCH * FEAT];
__device__ uint32_t       g_hb[2][BATCH * FEAT / 2];
__device__ __nv_bfloat16  g_E[2][(size_t)NDATA * BATCH];
__device__ double         g_Z[2];
__device__ double         g_L;
__device__ int            g_bars[4];
__device__ int            g_done;

// ---------------- helpers ----------------
__device__ __forceinline__ void ldsm_x4(uint32_t* r, uint32_t addr) {
    asm volatile("ldmatrix.sync.aligned.m8n8.x4.shared.b16 {%0,%1,%2,%3}, [%4];"
                 : "=r"(r[0]), "=r"(r[1]), "=r"(r[2]), "=r"(r[3]) : "r"(addr));
}
__device__ __forceinline__ void mma_bf16(float* c, const uint32_t* a, uint32_t b0, uint32_t b1) {
    asm volatile("mma.sync.aligned.m16n8k16.row.col.f32.bf16.bf16.f32 "
                 "{%0,%1,%2,%3}, {%4,%5,%6,%7}, {%8,%9}, {%0,%1,%2,%3};"
                 : "+f"(c[0]), "+f"(c[1]), "+f"(c[2]), "+f"(c[3])
                 : "r"(a[0]), "r"(a[1]), "r"(a[2]), "r"(a[3]), "r"(b0), "r"(b1));
}
__device__ __forceinline__ uint32_t pack_bf2(float x, float y) {
    __nv_bfloat162 h2 = __floats2bfloat162_rn(x, y);
    return *reinterpret_cast<uint32_t*>(&h2);
}
__device__ __forceinline__ float ld_e_cg(const __nv_bfloat16* p) {
    unsigned short v;
    asm volatile("ld.global.cg.u16 %0, [%1];" : "=h"(v) : "l"(p));
    __nv_bfloat16 b;
    *reinterpret_cast<unsigned short*>(&b) = v;
    return __bfloat162float(b);
}
// grid-wide spin barrier (all NB blocks co-resident by construction)
__device__ __forceinline__ void gbar(int idx) {
    __syncthreads();
    if (threadIdx.x == 0) {
        __threadfence();
        atomicAdd(&g_bars[idx], 1);
        while (*(volatile int*)&g_bars[idx] < NB) __nanosleep(100);
    }
    __syncthreads();
}

// ================= the one kernel =================
__global__ __launch_bounds__(256, 2) void k_fused(
    const float* __restrict__ fs, const float* __restrict__ ft,
    const int*   __restrict__ samp,
    const float* __restrict__ ws, const float* __restrict__ bsv,
    const float* __restrict__ wt, const float* __restrict__ btv,
    const float* __restrict__ mem_v1, const float* __restrict__ mem_v2,
    float* __restrict__ out)
{
    __shared__ __align__(16) char s_raw[25600];
    __shared__ float s_red[8];
    __shared__ float s_z;

    const int u   = blockIdx.x;
    const int tid = threadIdx.x;

    // ---------------- P0: embed GEMM, split-K fp32 (blocks 0..127) ----------------
    if (u < 2 * NSPLIT) {
        const int which = u >> 6;
        const int split = u & 63;
        const float* feat = which ? ft : fs;
        const float* w    = which ? wt : ws;
        const int k0 = split * 32;

        float* sf = reinterpret_cast<float*>(s_raw);            // 64 x 33
        float* sw = sf + BATCH * 33;                            // 128 x 33

        for (int i = tid; i < BATCH * 32; i += 256) {
            int b = i >> 5, kk = i & 31;
            sf[b * 33 + kk] = feat[b * KDIM + k0 + kk];
        }
        for (int i = tid; i < FEAT * 32; i += 256) {
            int d = i >> 5, kk = i & 31;
            sw[d * 33 + kk] = w[d * KDIM + k0 + kk];
        }
        __syncthreads();

        const int d0 = (tid >> 4) * 8, b0 = (tid & 15) * 4;
        float acc[4][8];
#pragma unroll
        for (int i = 0; i < 4; i++)
#pragma unroll
            for (int j = 0; j < 8; j++) acc[i][j] = 0.f;

#pragma unroll 4
        for (int kk = 0; kk < 32; kk++) {
            float fv[4], wv[8];
#pragma unroll
            for (int i = 0; i < 4; i++) fv[i] = sf[(b0 + i) * 33 + kk];
#pragma unroll
            for (int j = 0; j < 8; j++) wv[j] = sw[(d0 + j) * 33 + kk];
#pragma unroll
            for (int i = 0; i < 4; i++)
#pragma unroll
                for (int j = 0; j < 8; j++) acc[i][j] += fv[i] * wv[j];
        }
        float* outp = g_partial[which][split];
#pragma unroll
        for (int i = 0; i < 4; i++)
#pragma unroll
            for (int j = 0; j < 8; j++)
                outp[(b0 + i) * FEAT + d0 + j] = acc[i][j];
    }
    gbar(0);

    // ---------------- P1: reduce splits + bias + l2norm + pack bf16 ----------------
    if (u < 128) {
        const int which = u >> 6;
        const int b     = u & 63;
        const float* bias = which ? btv : bsv;
        float s = 0.f, v = 0.f;
        if (tid < 128) {
            const int d = tid;
#pragma unroll 8
            for (int sp = 0; sp < NSPLIT; sp++)
                s += __ldcg(&g_partial[which][sp][b * FEAT + d]);
            s += bias[d];
            float sq = s * s;
#pragma unroll
            for (int o = 16; o; o >>= 1) sq += __shfl_xor_sync(0xffffffffu, sq, o);
            if ((d & 31) == 0) s_red[d >> 5] = sq;
        }
        __syncthreads();
        if (tid < 128) {
            const float tot = s_red[0] + s_red[1] + s_red[2] + s_red[3];
            v = s * rsqrtf(tot);
            const float vn = __shfl_down_sync(0xffffffffu, v, 1);
            if ((tid & 1) == 0)
                g_hb[which][(b * FEAT + tid) >> 1] = pack_bf2(v, vn);
        }
    }
    gbar(1);

    // ---------------- P2: dense logits GEMM + fused exp, static schedule ----------------
    const int bank = (u >= NBB) ? 1 : 0;
    const int bx = u - bank * NBB;
    {
        const float* __restrict__ mem = bank ? mem_v1 : mem_v2;
        uint16_t* Vs = reinterpret_cast<uint16_t*>(s_raw);       // 64 x SA bf16

        for (int i = tid; i < BATCH * 64; i += 256) {
            const int row = i >> 6, c2 = i & 63;
            *reinterpret_cast<uint32_t*>(&Vs[row * SA + c2 * 2]) =
                __ldcg(&g_hb[bank][i]);
        }
        __syncthreads();

        const uint32_t v_base = (uint32_t)__cvta_generic_to_shared(Vs);
        const int lane = tid & 31, warp = tid >> 5;
        const int lr = lane & 7, q = lane >> 3;
        const int b_row = lr + ((q >> 1) << 3);
        const int b_kh  = (q & 1) << 3;
        uint32_t* Eb = reinterpret_cast<uint32_t*>(g_E[bank]);

        for (int tile = bx; tile < NTILE; tile += NBB) {
            const int r_base = tile * RBLK;
            const int row0 = r_base + warp * 16 + (lane >> 2);
            const int row1 = row0 + 8;
            const int rc0 = row0 < NDATA ? row0 : NDATA - 1;
            const int rc1 = row1 < NDATA ? row1 : NDATA - 1;
            const float* p0 = mem + (size_t)rc0 * FEAT + (lane & 3) * 2;
            const float* p1 = mem + (size_t)rc1 * FEAT + (lane & 3) * 2;

            // front-batch the whole A tile: 32 independent LDG.64 per thread
            float2 rbuf[32];
#pragma unroll
            for (int ks = 0; ks < 8; ks++) {
                rbuf[ks * 4 + 0] = __ldcs(reinterpret_cast<const float2*>(p0 + ks * 16));
                rbuf[ks * 4 + 1] = __ldcs(reinterpret_cast<const float2*>(p1 + ks * 16));
                rbuf[ks * 4 + 2] = __ldcs(reinterpret_cast<const float2*>(p0 + ks * 16 + 8));
                rbuf[ks * 4 + 3] = __ldcs(reinterpret_cast<const float2*>(p1 + ks * 16 + 8));
            }

            float acc[8][4];
#pragma unroll
            for (int f = 0; f < 8; f++)
#pragma unroll
                for (int e = 0; e < 4; e++) acc[f][e] = 0.f;

#pragma unroll
            for (int ks = 0; ks < 8; ks++) {
                uint32_t a[4];
#pragma unroll
                for (int e = 0; e < 4; e++)
                    a[e] = pack_bf2(rbuf[ks * 4 + e].x, rbuf[ks * 4 + e].y);
                const int k0 = ks * 16;
#pragma unroll
                for (int nt = 0; nt < 4; nt++) {
                    uint32_t bb[4];
                    ldsm_x4(bb, v_base + (uint32_t)((nt * 16 + b_row) * SA + k0 + b_kh) * 2u);
                    mma_bf16(acc[nt * 2 + 0], a, bb[0], bb[1]);
                    mma_bf16(acc[nt * 2 + 1], a, bb[2], bb[3]);
                }
            }

            const int cbase = (lane & 3) * 2;
#pragma unroll
            for (int f = 0; f < 8; f++) {
                const int c = (f >> 1) * 16 + (f & 1) * 8 + cbase;
                if (row0 < NDATA)
                    Eb[(size_t)row0 * (BATCH / 2) + (c >> 1)] =
                        pack_bf2(__expf(acc[f][0] * NCE_T_INV), __expf(acc[f][1] * NCE_T_INV));
                if (row1 < NDATA)
                    Eb[(size_t)row1 * (BATCH / 2) + (c >> 1)] =
                        pack_bf2(__expf(acc[f][2] * NCE_T_INV), __expf(acc[f][3] * NCE_T_INV));
            }
        }
    }
    gbar(2);

    // ---------------- P3: gather into registers + Z ----------------
    const int pbase = bx * 256 + tid;
    float gv[GITER];
    {
#pragma unroll
        for (int i = 0; i < GITER; i++) {
            const int p = pbase + i * GSTRIDE;
            gv[i] = 0.f;
            if (p < NPAIR) {
                const int s = __ldg(&samp[p]);
                const int b = p / NSAMP;
                gv[i] = ld_e_cg(&g_E[bank][(size_t)s * BATCH + b]);
            }
        }
        float lsum = 0.f;
#pragma unroll
        for (int i = 0; i < GITER; i++) lsum += gv[i];
#pragma unroll
        for (int o = 16; o; o >>= 1) lsum += __shfl_xor_sync(0xffffffffu, lsum, o);
        if ((tid & 31) == 0) s_red[tid >> 5] = lsum;
        __syncthreads();
        if (tid == 0) {
            double tot = 0.0;
#pragma unroll
            for (int i = 0; i < 8; i++) tot += (double)s_red[i];
            atomicAdd(&g_Z[bank], tot);
        }
    }
    gbar(3);

    // ---------------- P4: loss from registers (batched logs) ----------------
    {
        if (tid == 0) {
            const double Zv = *(volatile double*)&g_Z[bank];
            s_z = (float)(Zv * ((double)NDATA / (double)NPAIR));
        }
        __syncthreads();
        const float zinv = 1.0f / s_z;

        float lsum = 0.f;
        float pn = 1.f, pd = 1.f;
#pragma unroll
        for (int i = 0; i < GITER; i++) {
            const int p = pbase + i * GSTRIDE;
            if (p < NPAIR) {
                const float x = gv[i] * zinv;
                const int b = p / NSAMP;
                const bool pos = (p - b * NSAMP) == 0;
                pn *= pos ? x : M_CONST;
                pd *= x + M_CONST + EPS_C;
            }
            if (i == 13 || i == GITER - 1) {      // two batches of 14
                lsum += __logf(pn / pd);
                pn = 1.f; pd = 1.f;
            }
        }
#pragma unroll
        for (int o = 16; o; o >>= 1) lsum += __shfl_xor_sync(0xffffffffu, lsum, o);
        __syncthreads();
        if ((tid & 31) == 0) s_red[tid >> 5] = lsum;
        __syncthreads();
        if (tid == 0) {
            double tot = 0.0;
#pragma unroll
            for (int i = 0; i < 8; i++) tot += (double)s_red[i];
            atomicAdd(&g_L, tot);
            __threadfence();
            const int v = atomicAdd(&g_done, 1);
            if (v == NB - 1) {
                const double L = *(volatile double*)&g_L;
                out[0] = (float)(-L / (double)BATCH);
                // reset all state for the next graph replay
                g_Z[0] = 0.0; g_Z[1] = 0.0; g_L = 0.0;
                g_bars[0] = g_bars[1] = g_bars[2] = g_bars[3] = 0;
                g_done = 0;
                __threadfence();
            }
        }
    }
}

// ---------------- launcher: ONE kernel ----------------
extern "C" void kernel_launch(void* const* d_in, const int* in_sizes, int n_in,
                              void* d_out, int out_size) {
    const float* feat_s     = (const float*)d_in[0];
    const float* feat_t     = (const float*)d_in[1];
    // d_in[2] = idx (unused; positives already in sample_idx[:,0])
    const int*   sample_idx = (const int*)d_in[3];
    const float* w_s        = (const float*)d_in[4];
    const float* b_s        = (const float*)d_in[5];
    const float* w_t        = (const float*)d_in[6];
    const float* b_t        = (const float*)d_in[7];
    const float* mem_v1     = (const float*)d_in[8];
    const float* mem_v2     = (const float*)d_in[9];
    float* out = (float*)d_out;

    k_fused<<<NB, 256>>>(feat_s, feat_t, sample_idx,
                         w_s, b_s, w_t, b_t, mem_v1, mem_v2, out);
}